// round 1
// baseline (speedup 1.0000x reference)
#include <cuda_runtime.h>

#define BB 2
#define QL 1024
#define ML 1024
#define KLEN 2048
#define EMB 1024
#define NH 16
#define DH 64

// ---------------- scratch (static device, allocation-free) ----------------
__device__ float g_Q[BB * QL * EMB];               // [b,q,h,d]
__device__ float g_K[BB * KLEN * EMB];             // [b,k,h,d]
__device__ float g_V[BB * KLEN * EMB];             // [b,k,h,d]
__device__ float g_R[KLEN * EMB];                  // [p,h,d]
__device__ float g_BD[(size_t)BB * NH * QL * KLEN];// pre-shifted BD [b,h,q,j]
__device__ float g_AO[BB * QL * EMB];              // attention out [b,q,h*d]
__device__ float g_X[BB * QL * EMB];               // pre-LN residual sum

// ---------------- generic 128x128x8 SGEMM, N=K=1024 ----------------
// mode 0: A row m -> A + m*1024
// mode 1: cat(member, w) gather: rows [b*2048 .. b*2048+1023] from A(member),
//         rows [.. +2047] from A2(w)
__global__ __launch_bounds__(256) void sgemm128(
    const float* __restrict__ A, const float* __restrict__ A2,
    const float* __restrict__ W, float* __restrict__ C,
    const float* __restrict__ resid, int mode)
{
    __shared__ float As[8][132];
    __shared__ float Bs[8][128];
    const int tid = threadIdx.x;
    const int m0 = blockIdx.y * 128;
    const int n0 = blockIdx.x * 128;

    const int arow = tid >> 1;
    const int acol = (tid & 1) << 2;
    const int m = m0 + arow;
    const float* asrc;
    if (mode == 0) {
        asrc = A + (size_t)m * EMB;
    } else {
        int b = m >> 11, t = m & 2047;
        asrc = (t < ML) ? (A + ((size_t)b * ML + t) * EMB)
                        : (A2 + ((size_t)b * QL + (t - ML)) * EMB);
    }
    const int brow = tid >> 5;
    const int bcol = (tid & 31) << 2;
    const float* bsrc = W + (size_t)brow * EMB + n0 + bcol;

    const int tx = tid & 15, ty = tid >> 4;

    float acc[8][8];
#pragma unroll
    for (int i = 0; i < 8; i++)
#pragma unroll
        for (int j = 0; j < 8; j++) acc[i][j] = 0.f;

    float4 av = *(const float4*)(asrc + acol);
    float4 bv = *(const float4*)(bsrc);

    for (int k0 = 0; k0 < EMB; k0 += 8) {
        __syncthreads();
        As[acol + 0][arow] = av.x;
        As[acol + 1][arow] = av.y;
        As[acol + 2][arow] = av.z;
        As[acol + 3][arow] = av.w;
        *(float4*)&Bs[brow][bcol] = bv;
        __syncthreads();
        if (k0 + 8 < EMB) {
            av = *(const float4*)(asrc + k0 + 8 + acol);
            bv = *(const float4*)(bsrc + (size_t)(k0 + 8) * EMB);
        }
#pragma unroll
        for (int k = 0; k < 8; k++) {
            float4 a0 = *(const float4*)&As[k][ty * 4];
            float4 a1 = *(const float4*)&As[k][64 + ty * 4];
            float4 b0 = *(const float4*)&Bs[k][tx * 4];
            float4 b1 = *(const float4*)&Bs[k][64 + tx * 4];
            float a[8] = {a0.x, a0.y, a0.z, a0.w, a1.x, a1.y, a1.z, a1.w};
            float bb[8] = {b0.x, b0.y, b0.z, b0.w, b1.x, b1.y, b1.z, b1.w};
#pragma unroll
            for (int i = 0; i < 8; i++)
#pragma unroll
                for (int j = 0; j < 8; j++) acc[i][j] += a[i] * bb[j];
        }
    }

#pragma unroll
    for (int ih = 0; ih < 2; ih++)
#pragma unroll
        for (int r = 0; r < 4; r++) {
            int row = m0 + ih * 64 + ty * 4 + r;
#pragma unroll
            for (int jh = 0; jh < 2; jh++) {
                int col = n0 + jh * 64 + tx * 4;
                float4 v;
                v.x = acc[ih * 4 + r][jh * 4 + 0];
                v.y = acc[ih * 4 + r][jh * 4 + 1];
                v.z = acc[ih * 4 + r][jh * 4 + 2];
                v.w = acc[ih * 4 + r][jh * 4 + 3];
                if (resid) {
                    float4 rv = *(const float4*)(resid + (size_t)row * EMB + col);
                    v.x += rv.x; v.y += rv.y; v.z += rv.z; v.w += rv.w;
                }
                *(float4*)(C + (size_t)row * EMB + col) = v;
            }
        }
}

// ---------------- BD = (Q + r_r_bias) @ R^T, stored pre-shifted ----------------
// BD_shifted[b,h,i,j] = dot(q_i + rrb, rr[j - i + 1023]); write j = p - 1023 + i
__global__ __launch_bounds__(256) void bd_gemm(const float* __restrict__ rrb)
{
    const int pt = blockIdx.x, it = blockIdx.y, bh = blockIdx.z;
    const int i0 = it * 64, p0 = pt * 64;
    if (i0 + p0 + 126 < QL - 1) return;  // whole tile maps to j < 0
    const int b = bh >> 4, h = bh & 15;

    __shared__ float Qs[64 * 65];
    __shared__ float Rs[64 * 65];
    const int tid = threadIdx.x;

#pragma unroll
    for (int u = 0; u < 4; u++) {
        int f4 = tid + 256 * u;
        int rw = f4 >> 4;
        int d4 = (f4 & 15) << 2;
        float4 q = *(const float4*)&g_Q[(((size_t)b * QL + i0 + rw) * NH + h) * DH + d4];
        float4 bi = *(const float4*)&rrb[h * DH + d4];
        Qs[rw * 65 + d4 + 0] = q.x + bi.x;
        Qs[rw * 65 + d4 + 1] = q.y + bi.y;
        Qs[rw * 65 + d4 + 2] = q.z + bi.z;
        Qs[rw * 65 + d4 + 3] = q.w + bi.w;
        float4 rv = *(const float4*)&g_R[((size_t)(p0 + rw) * NH + h) * DH + d4];
        Rs[rw * 65 + d4 + 0] = rv.x;
        Rs[rw * 65 + d4 + 1] = rv.y;
        Rs[rw * 65 + d4 + 2] = rv.z;
        Rs[rw * 65 + d4 + 3] = rv.w;
    }
    __syncthreads();

    const int tx = tid & 15, ty = tid >> 4;
    float acc[4][4];
#pragma unroll
    for (int r = 0; r < 4; r++)
#pragma unroll
        for (int c = 0; c < 4; c++) acc[r][c] = 0.f;

#pragma unroll 8
    for (int d = 0; d < 64; d++) {
        float a[4], bvv[4];
#pragma unroll
        for (int r = 0; r < 4; r++) a[r] = Qs[(ty * 4 + r) * 65 + d];
#pragma unroll
        for (int c = 0; c < 4; c++) bvv[c] = Rs[(tx * 4 + c) * 65 + d];
#pragma unroll
        for (int r = 0; r < 4; r++)
#pragma unroll
            for (int c = 0; c < 4; c++) acc[r][c] += a[r] * bvv[c];
    }

    float* bdb = g_BD + (size_t)(b * NH + h) * QL * KLEN;
#pragma unroll
    for (int r = 0; r < 4; r++) {
        int gi = i0 + ty * 4 + r;
#pragma unroll
        for (int c = 0; c < 4; c++) {
            int gp = p0 + tx * 4 + c;
            int j = gp - (QL - 1) + gi;
            if (j >= 0) bdb[(size_t)gi * KLEN + j] = acc[r][c];
        }
    }
}

// ---------------- flash attention (fp32, q-tile 64, k-tile 64) ----------------
__global__ __launch_bounds__(256) void flash_kernel(const float* __restrict__ rwb)
{
    extern __shared__ float sm[];
    float* Qw = sm;
    float* Ks = sm + 64 * 65;
    float* Vs = sm + 2 * 64 * 65;
    float* Ps = sm + 3 * 64 * 65;

    const int qt = blockIdx.x, h = blockIdx.y, b = blockIdx.z;
    const int qi0 = qt * 64;
    const int tid = threadIdx.x, tx = tid & 15, ty = tid >> 4;

#pragma unroll
    for (int u = 0; u < 4; u++) {
        int f4 = tid + 256 * u;
        int rw = f4 >> 4, d4 = (f4 & 15) << 2;
        float4 q = *(const float4*)&g_Q[(((size_t)b * QL + qi0 + rw) * NH + h) * DH + d4];
        float4 bi = *(const float4*)&rwb[h * DH + d4];
        Qw[rw * 65 + d4 + 0] = q.x + bi.x;
        Qw[rw * 65 + d4 + 1] = q.y + bi.y;
        Qw[rw * 65 + d4 + 2] = q.z + bi.z;
        Qw[rw * 65 + d4 + 3] = q.w + bi.w;
    }

    float o[4][4];
    float mr[4], lr[4];
#pragma unroll
    for (int r = 0; r < 4; r++) {
        mr[r] = -1e30f; lr[r] = 0.f;
#pragma unroll
        for (int c = 0; c < 4; c++) o[r][c] = 0.f;
    }

    const float* bdb = g_BD + (size_t)(b * NH + h) * QL * KLEN;
    const float LOG2E = 1.4426950408889634f;
    const float sc = 0.03125f;  // 1/sqrt(1024)

    const int nkt = qt + 17;
    for (int kt = 0; kt < nkt; kt++) {
        const int kj0 = kt * 64;
        __syncthreads();
#pragma unroll
        for (int u = 0; u < 4; u++) {
            int f4 = tid + 256 * u;
            int rw = f4 >> 4, d4 = (f4 & 15) << 2;
            size_t go = (((size_t)b * KLEN + kj0 + rw) * NH + h) * DH + d4;
            float4 kv = *(const float4*)&g_K[go];
            Ks[rw * 65 + d4 + 0] = kv.x;
            Ks[rw * 65 + d4 + 1] = kv.y;
            Ks[rw * 65 + d4 + 2] = kv.z;
            Ks[rw * 65 + d4 + 3] = kv.w;
            float4 vv = *(const float4*)&g_V[go];
            Vs[rw * 65 + d4 + 0] = vv.x;
            Vs[rw * 65 + d4 + 1] = vv.y;
            Vs[rw * 65 + d4 + 2] = vv.z;
            Vs[rw * 65 + d4 + 3] = vv.w;
        }
        __syncthreads();

        float s[4][4];
#pragma unroll
        for (int r = 0; r < 4; r++)
#pragma unroll
            for (int c = 0; c < 4; c++) s[r][c] = 0.f;

#pragma unroll 8
        for (int d = 0; d < 64; d++) {
            float a[4], kk[4];
#pragma unroll
            for (int r = 0; r < 4; r++) a[r] = Qw[(ty * 4 + r) * 65 + d];
#pragma unroll
            for (int c = 0; c < 4; c++) kk[c] = Ks[(tx * 4 + c) * 65 + d];
#pragma unroll
            for (int r = 0; r < 4; r++)
#pragma unroll
                for (int c = 0; c < 4; c++) s[r][c] += a[r] * kk[c];
        }

#pragma unroll
        for (int r = 0; r < 4; r++) {
            int gi = qi0 + ty * 4 + r;
            float4 bd = *(const float4*)&bdb[(size_t)gi * KLEN + kj0 + tx * 4];
            float bda[4] = {bd.x, bd.y, bd.z, bd.w};
            int jlim = gi + ML - kj0;  // local j <= jlim is unmasked
#pragma unroll
            for (int c = 0; c < 4; c++) {
                int jl = tx * 4 + c;
                s[r][c] = (jl <= jlim) ? (s[r][c] + bda[c]) * sc : -1e30f;
            }
        }

        // online softmax update
#pragma unroll
        for (int r = 0; r < 4; r++) {
            float mx = fmaxf(fmaxf(s[r][0], s[r][1]), fmaxf(s[r][2], s[r][3]));
#pragma unroll
            for (int w = 1; w < 16; w <<= 1)
                mx = fmaxf(mx, __shfl_xor_sync(0xffffffff, mx, w));
            float mnew = fmaxf(mr[r], mx);
            float scal = exp2f((mr[r] - mnew) * LOG2E);
            mr[r] = mnew;
            lr[r] *= scal;
#pragma unroll
            for (int c = 0; c < 4; c++) o[r][c] *= scal;
            float ps = 0.f;
#pragma unroll
            for (int c = 0; c < 4; c++) {
                float p = exp2f((s[r][c] - mnew) * LOG2E);
                Ps[(ty * 4 + r) * 65 + tx * 4 + c] = p;
                ps += p;
            }
#pragma unroll
            for (int w = 1; w < 16; w <<= 1)
                ps += __shfl_xor_sync(0xffffffff, ps, w);
            lr[r] += ps;
        }
        __syncthreads();

        // O += P @ V
#pragma unroll 8
        for (int j = 0; j < 64; j++) {
            float pv[4], vv[4];
#pragma unroll
            for (int r = 0; r < 4; r++) pv[r] = Ps[(ty * 4 + r) * 65 + j];
#pragma unroll
            for (int c = 0; c < 4; c++) vv[c] = Vs[j * 65 + tx * 4 + c];
#pragma unroll
            for (int r = 0; r < 4; r++)
#pragma unroll
                for (int c = 0; c < 4; c++) o[r][c] += pv[r] * vv[c];
        }
    }

#pragma unroll
    for (int r = 0; r < 4; r++) {
        int gi = qi0 + ty * 4 + r;
        float inv = 1.0f / lr[r];
        float4 ov;
        ov.x = o[r][0] * inv;
        ov.y = o[r][1] * inv;
        ov.z = o[r][2] * inv;
        ov.w = o[r][3] * inv;
        *(float4*)&g_AO[((size_t)b * QL + gi) * EMB + h * DH + tx * 4] = ov;
    }
}

// ---------------- layernorm over last dim (1024), eps=1e-3 ----------------
__global__ __launch_bounds__(256) void ln_kernel(
    const float* __restrict__ gamma, const float* __restrict__ beta,
    float* __restrict__ out)
{
    const int row = blockIdx.x;
    const int tid = threadIdx.x;
    const float* x = g_X + (size_t)row * EMB;
    float4 v = ((const float4*)x)[tid];
    float s = v.x + v.y + v.z + v.w;
    float s2 = v.x * v.x + v.y * v.y + v.z * v.z + v.w * v.w;
#pragma unroll
    for (int w = 1; w < 32; w <<= 1) {
        s += __shfl_xor_sync(0xffffffff, s, w);
        s2 += __shfl_xor_sync(0xffffffff, s2, w);
    }
    __shared__ float sh[16];
    __shared__ float red[2];
    int wid = tid >> 5, lid = tid & 31;
    if (lid == 0) { sh[wid] = s; sh[wid + 8] = s2; }
    __syncthreads();
    if (tid == 0) {
        float ts = 0.f, ts2 = 0.f;
#pragma unroll
        for (int i = 0; i < 8; i++) { ts += sh[i]; ts2 += sh[i + 8]; }
        red[0] = ts; red[1] = ts2;
    }
    __syncthreads();
    float mean = red[0] * (1.0f / EMB);
    float var = red[1] * (1.0f / EMB) - mean * mean;
    float rs = rsqrtf(var + 1e-3f);
    float4 g = ((const float4*)gamma)[tid];
    float4 bt = ((const float4*)beta)[tid];
    float4 ov;
    ov.x = (v.x - mean) * rs * g.x + bt.x;
    ov.y = (v.y - mean) * rs * g.y + bt.y;
    ov.z = (v.z - mean) * rs * g.z + bt.z;
    ov.w = (v.w - mean) * rs * g.w + bt.w;
    ((float4*)(out + (size_t)row * EMB))[tid] = ov;
}

// ---------------- launch ----------------
extern "C" void kernel_launch(void* const* d_in, const int* in_sizes, int n_in,
                              void* d_out, int out_size)
{
    const float* w      = (const float*)d_in[0];
    const float* r      = (const float*)d_in[1];
    /* d_in[2] = attn_mask: implied analytically (j > i + MEM_LEN) */
    const float* rwb    = (const float*)d_in[3];
    const float* rrb    = (const float*)d_in[4];
    const float* member = (const float*)d_in[5];
    const float* Wq     = (const float*)d_in[6];
    const float* Wk     = (const float*)d_in[7];
    const float* Wv     = (const float*)d_in[8];
    const float* Wr     = (const float*)d_in[9];
    const float* Wo     = (const float*)d_in[10];
    const float* gamma  = (const float*)d_in[11];
    const float* beta   = (const float*)d_in[12];
    float* out = (float*)d_out;

    float *gQ, *gK, *gV, *gR, *gAO, *gX;
    cudaGetSymbolAddress((void**)&gQ, g_Q);
    cudaGetSymbolAddress((void**)&gK, g_K);
    cudaGetSymbolAddress((void**)&gV, g_V);
    cudaGetSymbolAddress((void**)&gR, g_R);
    cudaGetSymbolAddress((void**)&gAO, g_AO);
    cudaGetSymbolAddress((void**)&gX, g_X);

    dim3 blk(256);
    // projections
    sgemm128<<<dim3(8, 16), blk>>>(w, nullptr, Wq, gQ, nullptr, 0);
    sgemm128<<<dim3(8, 32), blk>>>(member, w, Wk, gK, nullptr, 1);
    sgemm128<<<dim3(8, 32), blk>>>(member, w, Wv, gV, nullptr, 1);
    sgemm128<<<dim3(8, 16), blk>>>(r, nullptr, Wr, gR, nullptr, 0);
    // BD with fused rel_shift
    bd_gemm<<<dim3(32, 16, 32), blk>>>(rrb);
    // flash attention
    int smem = 4 * 64 * 65 * sizeof(float);
    cudaFuncSetAttribute(flash_kernel, cudaFuncAttributeMaxDynamicSharedMemorySize, smem);
    flash_kernel<<<dim3(16, NH, BB), blk, smem>>>(rwb);
    // output projection + residual
    sgemm128<<<dim3(8, 16), blk>>>(gAO, nullptr, Wo, gX, w, 0);
    // layernorm
    ln_kernel<<<BB * QL, blk>>>(gamma, beta, out);
}